// round 5
// baseline (speedup 1.0000x reference)
#include <cuda_runtime.h>
#include <cuda_bf16.h>

// ---------------- problem constants (dataset-fixed) ----------------
#define B_    32
#define H_    32
#define KVH_  8
#define G_    4
#define D_    128
#define SW_   4096
#define HID_  4096
#define QKVD_ 6144
#define POS_  2047          // current_pos (dataset constant)
#define L_    2048          // min(current_pos+1, SW)
#define CH_   32            // keys per attention chunk
#define NCH_  64            // L / CH
#define NHEAD_ 1024         // B * H
#define NBKV_  256          // B * KVH
#define SPLITS_ 32
#define KC_     (HID_ / SPLITS_)   // 128

typedef unsigned long long u64;

// ---------------- scratch (no allocations allowed) ----------------
__device__ __align__(16) float g_part[SPLITS_ * B_ * QKVD_];
__device__ __align__(16) float g_xqkv[B_ * QKVD_];
__device__ __align__(16) float g_q[B_ * H_ * D_];
__device__ __align__(16) float g_knew[B_ * KVH_ * D_];
__device__ __align__(16) float g_vnew[B_ * KVH_ * D_];
__device__ __align__(16) float g_attout[B_ * HID_];
__device__ __align__(16) float g_pml[NCH_ * NHEAD_ * 2];
__device__ __align__(16) float g_po [NCH_ * NHEAD_ * D_];

// ---------------- f32x2 helpers ----------------
__device__ __forceinline__ u64 pack2(float lo, float hi) {
    u64 r; asm("mov.b64 %0, {%1, %2};" : "=l"(r) : "f"(lo), "f"(hi)); return r;
}
__device__ __forceinline__ void unpack2(u64 v, float& lo, float& hi) {
    asm("mov.b64 {%0, %1}, %2;" : "=f"(lo), "=f"(hi) : "l"(v));
}
__device__ __forceinline__ u64 fma2(u64 a, u64 b, u64 c) {
    u64 d; asm("fma.rn.f32x2 %0, %1, %2, %3;" : "=l"(d) : "l"(a), "l"(b), "l"(c)); return d;
}

// ====================================================================
// Split-K GEMM partials with packed f32x2 math (32 splits of 128 k).
// Block = 128 threads, 256 cols (2 adjacent per thread), 32 rows packed
// into 16 u64 row-pair accumulators. X tile transposed in smem
// (broadcast LDS.64); W coalesced LDG.64.
// ====================================================================
__global__ void gemm_part(const float* __restrict__ Xin,
                          const float* __restrict__ W,
                          int N, int use_attout)
{
    const float* __restrict__ X = use_attout ? g_attout : Xin;
    __shared__ float xs[32][36];
    const int t  = threadIdx.x;            // 0..127
    const int j  = blockIdx.x * 256 + 2 * t;
    const int k0 = blockIdx.y * KC_;

    u64 acc[16][2];
#pragma unroll
    for (int r = 0; r < 16; r++) { acc[r][0] = 0ULL; acc[r][1] = 0ULL; }

    for (int kt = 0; kt < KC_; kt += 32) {
#pragma unroll
        for (int i = 0; i < 2; i++) {
            int slot = t + 128 * i;
            int m  = slot >> 3;
            int c4 = slot & 7;
            const float4 v = *(const float4*)&X[m * HID_ + k0 + kt + c4 * 4];
            xs[c4 * 4 + 0][m] = v.x;
            xs[c4 * 4 + 1][m] = v.y;
            xs[c4 * 4 + 2][m] = v.z;
            xs[c4 * 4 + 3][m] = v.w;
        }
        __syncthreads();

        const float* wp = &W[(size_t)(k0 + kt) * N + j];
#pragma unroll 8
        for (int kk = 0; kk < 32; kk++) {
            const float2 wv = *(const float2*)(wp + (size_t)kk * N);
            const u64 w0 = pack2(wv.x, wv.x);
            const u64 w1 = pack2(wv.y, wv.y);
            const u64* xr = (const u64*)&xs[kk][0];
#pragma unroll
            for (int r = 0; r < 16; r++) {
                u64 x2 = xr[r];
                acc[r][0] = fma2(x2, w0, acc[r][0]);
                acc[r][1] = fma2(x2, w1, acc[r][1]);
            }
        }
        __syncthreads();
    }

    float* op = g_part + (size_t)blockIdx.y * 32 * N;
#pragma unroll
    for (int r = 0; r < 16; r++) {
        float a, b;
        unpack2(acc[r][0], a, b);
        op[(size_t)(2 * r) * N + j]         = a;
        op[(size_t)(2 * r + 1) * N + j]     = b;
        unpack2(acc[r][1], a, b);
        op[(size_t)(2 * r) * N + j + 1]     = a;
        op[(size_t)(2 * r + 1) * N + j + 1] = b;
    }
}

// ---------------- split-K reduction ----------------
__global__ void reduce_part(float* __restrict__ outp, int total, int to_xqkv)
{
    float* o = to_xqkv ? g_xqkv : outp;
    int i = blockIdx.x * 256 + threadIdx.x;
    float a = 0.f;
#pragma unroll
    for (int s = 0; s < SPLITS_; s++) a += g_part[(size_t)s * total + i];
    o[i] = a;
}

// ====================================================================
// RoPE
// ====================================================================
__global__ void rope_kernel(const float* __restrict__ rot)
{
    __shared__ float xr[128];
    const int t   = threadIdx.x;
    const int blk = blockIdx.x;

    if (blk < 1024) {
        int b = blk >> 5, h = blk & 31;
        xr[t] = g_xqkv[b * QKVD_ + h * 128 + t];
        __syncthreads();
        float acc = 0.f;
#pragma unroll 8
        for (int d = 0; d < 128; d++)
            acc = fmaf(xr[d], rot[d * 128 + t], acc);
        g_q[blk * 128 + t] = acc * 0.08838834764831845f;
    } else {
        int kv = blk - 1024;
        int b = kv >> 3, kvh = kv & 7;
        xr[t] = g_xqkv[b * QKVD_ + 4096 + kvh * 128 + t];
        g_vnew[kv * 128 + t] = g_xqkv[b * QKVD_ + 5120 + kvh * 128 + t];
        __syncthreads();
        float acc = 0.f;
#pragma unroll 8
        for (int d = 0; d < 128; d++)
            acc = fmaf(xr[d], rot[d * 128 + t], acc);
        g_knew[kv * 128 + t] = acc;
    }
}

// ====================================================================
// Flash-decode attention. One (b,kvh,chunk-of-32) per block, 128 thr.
// ~45 KB smem -> 5 blocks/SM. K rows padded to 65 u64 (520B = 8 mod 256)
// so per-lane-row LDS.64 score reads are conflict-free. K and V both
// issued before first use (max MLP). Each k/v element read from smem
// once, used for all G=4 heads; packed f32x2 math throughout.
// smem: kbuf[32*65]u64 | vbuf[32*64]u64 | qs[4*32]f4 |
//       ss[4dc][4g][32p] | sfin[4][32] | probs[4][32] | pvp[4pg][4g][32]f4
// ====================================================================
#define ATT_SMEM_ 46336

__global__ __launch_bounds__(128) void attn_chunk(const float* __restrict__ cache_k,
                                                  const float* __restrict__ cache_v)
{
    extern __shared__ char smem_raw[];
    u64*    kbuf = (u64*)smem_raw;            // 32*65
    u64*    vbuf = kbuf + 32 * 65;            // 32*64
    float4* qs   = (float4*)(vbuf + 32 * 64); // 4*32
    float*  ss   = (float*)(qs + 128);        // 512
    float*  sfin = ss + 512;                  // 128
    float*  probs= sfin + 128;                // 128
    float4* pvp  = (float4*)(probs + 128);    // 4*4*32

    const int t   = threadIdx.x;       // 0..127
    const int bkv = blockIdx.x;        // b*8 + kvh
    const int c   = blockIdx.y;        // chunk
    const int p0  = c * CH_;

    // q heads (head index = bkv*4 + g)
    {
        int g = t >> 5, dq = t & 31;
        qs[g * 32 + dq] = *(const float4*)&g_q[(bkv * 4 + g) * 128 + dq * 4];
    }

    // K chunk: 32 rows x 32 float4 (p constant per warp, dq = lane)
#pragma unroll
    for (int i = 0; i < 8; i++) {
        int slot = t + 128 * i;
        int p = slot >> 5, dq = slot & 31;
        int gp = p0 + p;
        const float* src = (gp == POS_)
            ? (g_knew + bkv * D_)
            : (cache_k + ((size_t)bkv * SW_ + gp) * D_);
        float4 v = *(const float4*)&src[dq * 4];
        u64* dst = kbuf + p * 65 + dq * 2;
        dst[0] = ((const u64*)&v)[0];
        dst[1] = ((const u64*)&v)[1];
    }
    // V chunk (stride 64 u64 = float4-clean)
#pragma unroll
    for (int i = 0; i < 8; i++) {
        int slot = t + 128 * i;
        int p = slot >> 5, dq = slot & 31;
        int gp = p0 + p;
        const float* src = (gp == POS_)
            ? (g_vnew + bkv * D_)
            : (cache_v + ((size_t)bkv * SW_ + gp) * D_);
        ((float4*)vbuf)[p * 32 + dq] = *(const float4*)&src[dq * 4];
    }
    __syncthreads();

    // scores: thread = (p = lane, dc = warp); k u64 read once -> 4 heads
    {
        int p = t & 31, dc = t >> 5;
        const u64* kp = kbuf + p * 65 + dc * 16;
        const u64* q2 = (const u64*)qs;        // [g*64 + d2]
        u64 a0 = 0ULL, a1 = 0ULL, a2 = 0ULL, a3 = 0ULL;
#pragma unroll
        for (int i = 0; i < 16; i++) {
            u64 k2 = kp[i];
            int qi = dc * 16 + i;
            a0 = fma2(k2, q2[qi],       a0);
            a1 = fma2(k2, q2[64 + qi],  a1);
            a2 = fma2(k2, q2[128 + qi], a2);
            a3 = fma2(k2, q2[192 + qi], a3);
        }
        float lo, hi;
        unpack2(a0, lo, hi); ss[(dc * 4 + 0) * 32 + p] = lo + hi;
        unpack2(a1, lo, hi); ss[(dc * 4 + 1) * 32 + p] = lo + hi;
        unpack2(a2, lo, hi); ss[(dc * 4 + 2) * 32 + p] = lo + hi;
        unpack2(a3, lo, hi); ss[(dc * 4 + 3) * 32 + p] = lo + hi;
    }
    __syncthreads();

    // sum d-chunks: thread = (g = warp, p = lane)
    {
        int g = t >> 5, p = t & 31;
        sfin[g * 32 + p] = (ss[(0 * 4 + g) * 32 + p] + ss[(1 * 4 + g) * 32 + p])
                         + (ss[(2 * 4 + g) * 32 + p] + ss[(3 * 4 + g) * 32 + p]);
    }
    __syncthreads();

    // partial softmax: warp g handles head g (32 scores, 1/lane)
    {
        int warp = t >> 5, lane = t & 31;
        float s = sfin[warp * 32 + lane];
        float m = s;
#pragma unroll
        for (int o = 16; o > 0; o >>= 1)
            m = fmaxf(m, __shfl_xor_sync(0xffffffffu, m, o));
        float e = __expf(s - m);
        probs[warp * 32 + lane] = e;
        float l = e;
#pragma unroll
        for (int o = 16; o > 0; o >>= 1)
            l += __shfl_xor_sync(0xffffffffu, l, o);
        if (lane == 0) {
            int head = bkv * 4 + warp;
            g_pml[(c * NHEAD_ + head) * 2 + 0] = m;
            g_pml[(c * NHEAD_ + head) * 2 + 1] = l;
        }
    }
    __syncthreads();

    // pv: thread = (pg = warp, dq = lane), 8 p each; v read once -> 4 heads
    {
        int pg = t >> 5, dq = t & 31;
        u64 ax[4], ay[4];
#pragma unroll
        for (int g = 0; g < 4; g++) { ax[g] = 0ULL; ay[g] = 0ULL; }
#pragma unroll
        for (int pp = 0; pp < 8; pp++) {
            int p = pg * 8 + pp;
            const u64* v2 = vbuf + p * 64 + dq * 2;
            u64 va = v2[0], vb = v2[1];
#pragma unroll
            for (int g = 0; g < 4; g++) {
                float w = probs[g * 32 + p];
                u64 wd = pack2(w, w);
                ax[g] = fma2(va, wd, ax[g]);
                ay[g] = fma2(vb, wd, ay[g]);
            }
        }
#pragma unroll
        for (int g = 0; g < 4; g++) {
            float4 r;
            unpack2(ax[g], r.x, r.y);
            unpack2(ay[g], r.z, r.w);
            pvp[(pg * 4 + g) * 32 + dq] = r;
        }
    }
    __syncthreads();

    // reduce 4 p-groups: thread = (g = warp, dq = lane)
    {
        int g = t >> 5, dq = t & 31;
        float4 a = make_float4(0.f, 0.f, 0.f, 0.f);
#pragma unroll
        for (int pg = 0; pg < 4; pg++) {
            float4 v = pvp[(pg * 4 + g) * 32 + dq];
            a.x += v.x; a.y += v.y; a.z += v.z; a.w += v.w;
        }
        int head = bkv * 4 + g;
        *(float4*)&g_po[((size_t)c * NHEAD_ + head) * D_ + dq * 4] = a;
    }
}

// ---------------- combine per-chunk softmax partials ----------------
__global__ void combine_kernel()
{
    const int head = blockIdx.x;
    const int t    = threadIdx.x;

    float M = -1e30f;
#pragma unroll
    for (int c = 0; c < NCH_; c++)
        M = fmaxf(M, g_pml[(c * NHEAD_ + head) * 2]);

    float denom = 0.f, acc = 0.f;
    for (int c = 0; c < NCH_; c++) {
        float m = g_pml[(c * NHEAD_ + head) * 2 + 0];
        float l = g_pml[(c * NHEAD_ + head) * 2 + 1];
        float w = __expf(m - M);
        denom += w * l;
        acc = fmaf(w, g_po[((size_t)c * NHEAD_ + head) * D_ + t], acc);
    }
    g_attout[head * 128 + t] = acc / denom;
}

// ====================================================================
extern "C" void kernel_launch(void* const* d_in, const int* in_sizes, int n_in,
                              void* d_out, int out_size)
{
    const float* x    = (const float*)d_in[0];
    const float* wqkv = (const float*)d_in[1];
    const float* wo   = (const float*)d_in[2];
    const float* rot  = (const float*)d_in[3];
    const float* ck   = (const float*)d_in[4];
    const float* cv   = (const float*)d_in[5];
    float* out = (float*)d_out;

    static int smem_set = 0;
    if (!smem_set) {
        cudaFuncSetAttribute(attn_chunk,
                             cudaFuncAttributeMaxDynamicSharedMemorySize,
                             ATT_SMEM_);
        smem_set = 1;
    }

    // 1) QKV projection (split-K 32) + reduce
    gemm_part<<<dim3(24, SPLITS_), 128>>>(x, wqkv, QKVD_, 0);
    reduce_part<<<768, 256>>>(nullptr, B_ * QKVD_, 1);

    // 2) RoPE
    rope_kernel<<<1280, 128>>>(rot);

    // 3) flash-decode attention (64 chunks of 32 keys)
    attn_chunk<<<dim3(NBKV_, NCH_), 128, ATT_SMEM_>>>(ck, cv);
    combine_kernel<<<NHEAD_, 128>>>();

    // 4) output projection + reduce into d_out
    gemm_part<<<dim3(16, SPLITS_), 128>>>(nullptr, wo, HID_, 1);
    reduce_part<<<512, 256>>>(out, B_ * HID_, 0);
}

// round 7
// speedup vs baseline: 1.2496x; 1.2496x over previous
#include <cuda_runtime.h>
#include <cuda_bf16.h>

// ---------------- problem constants (dataset-fixed) ----------------
#define B_    32
#define H_    32
#define KVH_  8
#define G_    4
#define D_    128
#define SW_   4096
#define HID_  4096
#define QKVD_ 6144
#define POS_  2047          // current_pos (dataset constant)
#define L_    2048          // min(current_pos+1, SW)
#define CH_   32            // keys per attention chunk
#define CPG_  4             // chunks per block (pipelined)
#define NCHG_ 16            // chunk groups = L/(CH*CPG)
#define NHEAD_ 1024         // B * H
#define NBKV_  256          // B * KVH
#define SPLITS_ 16
#define KC_     (HID_ / SPLITS_)   // 256

typedef unsigned long long u64;

// ---------------- scratch (no allocations allowed) ----------------
__device__ __align__(16) float g_part[SPLITS_ * B_ * QKVD_];
__device__ __align__(16) float g_xqkv[B_ * QKVD_];
__device__ __align__(16) float g_q[B_ * H_ * D_];
__device__ __align__(16) float g_knew[B_ * KVH_ * D_];
__device__ __align__(16) float g_vnew[B_ * KVH_ * D_];
__device__ __align__(16) float g_attout[B_ * HID_];
__device__ __align__(16) float g_pml[NCHG_ * NHEAD_ * 2];
__device__ __align__(16) float g_po [NCHG_ * NHEAD_ * D_];

// ---------------- f32x2 / async helpers ----------------
__device__ __forceinline__ u64 pack2(float lo, float hi) {
    u64 r; asm("mov.b64 %0, {%1, %2};" : "=l"(r) : "f"(lo), "f"(hi)); return r;
}
__device__ __forceinline__ void unpack2(u64 v, float& lo, float& hi) {
    asm("mov.b64 {%0, %1}, %2;" : "=f"(lo), "=f"(hi) : "l"(v));
}
__device__ __forceinline__ u64 fma2(u64 a, u64 b, u64 c) {
    u64 d; asm("fma.rn.f32x2 %0, %1, %2, %3;" : "=l"(d) : "l"(a), "l"(b), "l"(c)); return d;
}
__device__ __forceinline__ unsigned su32(const void* p) {
    return (unsigned)__cvta_generic_to_shared(p);
}
__device__ __forceinline__ void cp16(unsigned dst, const void* src) {
    asm volatile("cp.async.cg.shared.global [%0], [%1], 16;" :: "r"(dst), "l"(src));
}
__device__ __forceinline__ void cp8(unsigned dst, const void* src) {
    asm volatile("cp.async.ca.shared.global [%0], [%1], 8;" :: "r"(dst), "l"(src));
}
__device__ __forceinline__ void cp_commit() {
    asm volatile("cp.async.commit_group;");
}

// ====================================================================
// Split-K GEMM partials with packed f32x2 math (16 splits of 256 k).
// Block = 128 threads, 256 cols (2 adjacent per thread), 32 rows packed
// into 16 u64 row-pair accumulators.
// ====================================================================
__global__ void gemm_part(const float* __restrict__ Xin,
                          const float* __restrict__ W,
                          int N, int use_attout)
{
    const float* __restrict__ X = use_attout ? g_attout : Xin;
    __shared__ float xs[32][36];
    const int t  = threadIdx.x;            // 0..127
    const int j  = blockIdx.x * 256 + 2 * t;
    const int k0 = blockIdx.y * KC_;

    u64 acc[16][2];
#pragma unroll
    for (int r = 0; r < 16; r++) { acc[r][0] = 0ULL; acc[r][1] = 0ULL; }

    for (int kt = 0; kt < KC_; kt += 32) {
#pragma unroll
        for (int i = 0; i < 2; i++) {
            int slot = t + 128 * i;
            int m  = slot >> 3;
            int c4 = slot & 7;
            const float4 v = *(const float4*)&X[m * HID_ + k0 + kt + c4 * 4];
            xs[c4 * 4 + 0][m] = v.x;
            xs[c4 * 4 + 1][m] = v.y;
            xs[c4 * 4 + 2][m] = v.z;
            xs[c4 * 4 + 3][m] = v.w;
        }
        __syncthreads();

        const float* wp = &W[(size_t)(k0 + kt) * N + j];
#pragma unroll 8
        for (int kk = 0; kk < 32; kk++) {
            const float2 wv = *(const float2*)(wp + (size_t)kk * N);
            const u64 w0 = pack2(wv.x, wv.x);
            const u64 w1 = pack2(wv.y, wv.y);
            const u64* xr = (const u64*)&xs[kk][0];
#pragma unroll
            for (int r = 0; r < 16; r++) {
                u64 x2 = xr[r];
                acc[r][0] = fma2(x2, w0, acc[r][0]);
                acc[r][1] = fma2(x2, w1, acc[r][1]);
            }
        }
        __syncthreads();
    }

    float* op = g_part + (size_t)blockIdx.y * 32 * N;
#pragma unroll
    for (int r = 0; r < 16; r++) {
        float a, b;
        unpack2(acc[r][0], a, b);
        op[(size_t)(2 * r) * N + j]         = a;
        op[(size_t)(2 * r + 1) * N + j]     = b;
        unpack2(acc[r][1], a, b);
        op[(size_t)(2 * r) * N + j + 1]     = a;
        op[(size_t)(2 * r + 1) * N + j + 1] = b;
    }
}

// ---------------- split-K reduction ----------------
__global__ void reduce_part(float* __restrict__ outp, int total, int to_xqkv)
{
    float* o = to_xqkv ? g_xqkv : outp;
    int i = blockIdx.x * 256 + threadIdx.x;
    float a = 0.f;
#pragma unroll
    for (int s = 0; s < SPLITS_; s++) a += g_part[(size_t)s * total + i];
    o[i] = a;
}

// ====================================================================
// RoPE
// ====================================================================
__global__ void rope_kernel(const float* __restrict__ rot)
{
    __shared__ float xr[128];
    const int t   = threadIdx.x;
    const int blk = blockIdx.x;

    if (blk < 1024) {
        int b = blk >> 5, h = blk & 31;
        xr[t] = g_xqkv[b * QKVD_ + h * 128 + t];
        __syncthreads();
        float acc = 0.f;
#pragma unroll 8
        for (int d = 0; d < 128; d++)
            acc = fmaf(xr[d], rot[d * 128 + t], acc);
        g_q[blk * 128 + t] = acc * 0.08838834764831845f;
    } else {
        int kv = blk - 1024;
        int b = kv >> 3, kvh = kv & 7;
        xr[t] = g_xqkv[b * QKVD_ + 4096 + kvh * 128 + t];
        g_vnew[kv * 128 + t] = g_xqkv[b * QKVD_ + 5120 + kvh * 128 + t];
        __syncthreads();
        float acc = 0.f;
#pragma unroll 8
        for (int d = 0; d < 128; d++)
            acc = fmaf(xr[d], rot[d * 128 + t], acc);
        g_knew[kv * 128 + t] = acc;
    }
}

// ====================================================================
// Pipelined flash-decode attention.
// Block = 256 threads handles (bkv, group of 4 consecutive 32-key
// chunks) with double-buffered cp.async K/V tiles. Online softmax merge
// in registers -> one partial per group. K rows stride 65 u64 (520B):
// per-lane-row LDS.64 score reads conflict-free; K loaded via 8-byte
// cp.async (odd rows are only 8B-aligned). V rows stride 64 u64, 16B
// cp.async. ~71KB smem -> 3 blocks/SM.
// ====================================================================
#define ATT_SMEM_ (33280 + 32768 + 2048 + 4096 + 512 + 64)

__global__ __launch_bounds__(256) void attn_group(const float* __restrict__ cache_k,
                                                  const float* __restrict__ cache_v)
{
    extern __shared__ char smem_raw[];
    u64*    kbuf  = (u64*)smem_raw;                // [2][32*65]
    u64*    vbuf  = kbuf + 2 * 32 * 65;            // [2][32*64]
    float4* qs    = (float4*)(vbuf + 2 * 32 * 64); // [4*32]
    float*  ss    = (float*)(qs + 128);            // [8dc][4g][32p]
    float*  probs = ss + 1024;                     // [4g][32p]
    float*  Msm   = probs + 128;                   // [4]
    float*  Lsm   = Msm + 4;                       // [4]
    float*  Asm   = Lsm + 4;                       // [4] alpha

    const int t   = threadIdx.x;       // 0..255
    const int bkv = blockIdx.x;        // b*8 + kvh
    const int grp = blockIdx.y;        // chunk group
    const int c0  = grp * CPG_;

    // q heads
    if (t < 128) {
        int g = t >> 5, dq = t & 31;
        qs[g * 32 + dq] = *(const float4*)&g_q[(bkv * 4 + g) * 128 + dq * 4];
    }
    if (t < 4) { Msm[t] = -1e30f; Lsm[t] = 0.f; }

    // ---- async tile loader ----
    auto issue_chunk = [&](int cc, int buf) {
        const int p0 = (c0 + cc) * CH_;
        u64* kb = kbuf + buf * 32 * 65;
        u64* vb = vbuf + buf * 32 * 64;
#pragma unroll
        for (int i = 0; i < 4; i++) {
            int slot = t + 256 * i;            // 0..1023
            int p = slot >> 5, dq = slot & 31;
            int gp = p0 + p;
            const float* ks = (gp == POS_)
                ? (g_knew + bkv * D_)
                : (cache_k + ((size_t)bkv * SW_ + gp) * D_);
            unsigned d0 = su32(kb + p * 65 + dq * 2);
            cp8(d0,     ks + dq * 4);
            cp8(d0 + 8, ks + dq * 4 + 2);
        }
#pragma unroll
        for (int i = 0; i < 4; i++) {
            int slot = t + 256 * i;
            int p = slot >> 5, dq = slot & 31;
            int gp = p0 + p;
            const float* vs = (gp == POS_)
                ? (g_vnew + bkv * D_)
                : (cache_v + ((size_t)bkv * SW_ + gp) * D_);
            cp16(su32(vb + p * 64 + dq * 2), vs + dq * 4);
        }
        cp_commit();
    };

    issue_chunk(0, 0);

    u64 O = 0ULL;                      // running output: thread (g = t>>6, d2 = t&63)
    const int pvg  = t >> 6;
    const int pvd2 = t & 63;

#pragma unroll 1
    for (int cc = 0; cc < CPG_; cc++) {
        const int buf = cc & 1;
        if (cc < CPG_ - 1) {
            issue_chunk(cc + 1, buf ^ 1);
            asm volatile("cp.async.wait_group 1;");
        } else {
            asm volatile("cp.async.wait_group 0;");
        }
        __syncthreads();

        const u64* kb = kbuf + buf * 32 * 65;
        const u64* vb = vbuf + buf * 32 * 64;

        // scores: thread = (p = t&31, dc = t>>5 of 8); 16 d (8 u64) each
        {
            int p = t & 31, dc = t >> 5;
            const u64* kp = kb + p * 65 + dc * 8;
            const u64* q2 = (const u64*)qs;
            u64 a0 = 0ULL, a1 = 0ULL, a2 = 0ULL, a3 = 0ULL;
#pragma unroll
            for (int i = 0; i < 8; i++) {
                u64 k2 = kp[i];
                int qi = dc * 8 + i;
                a0 = fma2(k2, q2[qi],       a0);
                a1 = fma2(k2, q2[64 + qi],  a1);
                a2 = fma2(k2, q2[128 + qi], a2);
                a3 = fma2(k2, q2[192 + qi], a3);
            }
            float lo, hi;
            unpack2(a0, lo, hi); ss[(dc * 4 + 0) * 32 + p] = lo + hi;
            unpack2(a1, lo, hi); ss[(dc * 4 + 1) * 32 + p] = lo + hi;
            unpack2(a2, lo, hi); ss[(dc * 4 + 2) * 32 + p] = lo + hi;
            unpack2(a3, lo, hi); ss[(dc * 4 + 3) * 32 + p] = lo + hi;
        }
        __syncthreads();

        // sum d-chunks + online softmax update: warp g (t<128)
        if (t < 128) {
            int g = t >> 5, p = t & 31;
            float s = 0.f;
#pragma unroll
            for (int dc = 0; dc < 8; dc++)
                s += ss[(dc * 4 + g) * 32 + p];

            float mc = s;
#pragma unroll
            for (int o = 16; o > 0; o >>= 1)
                mc = fmaxf(mc, __shfl_xor_sync(0xffffffffu, mc, o));
            float Mold = Msm[g];
            float Mnew = fmaxf(Mold, mc);
            float e = __expf(s - Mnew);
            probs[g * 32 + p] = e;
            float l = e;
#pragma unroll
            for (int o = 16; o > 0; o >>= 1)
                l += __shfl_xor_sync(0xffffffffu, l, o);
            if (p == 0) {
                float alpha = __expf(Mold - Mnew);
                Asm[g] = alpha;
                Lsm[g] = Lsm[g] * alpha + l;
                Msm[g] = Mnew;
            }
        }
        __syncthreads();

        // pv with online rescale: thread = (g = t>>6, d2 = t&63)
        {
            float alpha = Asm[pvg];
            O = fma2(O, pack2(alpha, alpha), 0ULL);
            const float* pr = probs + pvg * 32;
#pragma unroll
            for (int p = 0; p < 32; p++) {
                float w = pr[p];
                O = fma2(vb[p * 64 + pvd2], pack2(w, w), O);
            }
        }
        __syncthreads();
    }

    // epilogue: one partial per group
    {
        int head = bkv * 4 + pvg;
        float o0, o1;
        unpack2(O, o0, o1);
        float2* dst = (float2*)&g_po[((size_t)grp * NHEAD_ + head) * D_ + pvd2 * 2];
        *dst = make_float2(o0, o1);
    }
    if (t < 4) {
        int head = bkv * 4 + t;
        g_pml[(grp * NHEAD_ + head) * 2 + 0] = Msm[t];
        g_pml[(grp * NHEAD_ + head) * 2 + 1] = Lsm[t];
    }
}

// ---------------- combine per-group softmax partials ----------------
__global__ void combine_kernel()
{
    const int head = blockIdx.x;
    const int t    = threadIdx.x;

    float M = -1e30f;
#pragma unroll
    for (int c = 0; c < NCHG_; c++)
        M = fmaxf(M, g_pml[(c * NHEAD_ + head) * 2]);

    float denom = 0.f, acc = 0.f;
#pragma unroll
    for (int c = 0; c < NCHG_; c++) {
        float m = g_pml[(c * NHEAD_ + head) * 2 + 0];
        float l = g_pml[(c * NHEAD_ + head) * 2 + 1];
        float w = __expf(m - M);
        denom += w * l;
        acc = fmaf(w, g_po[((size_t)c * NHEAD_ + head) * D_ + t], acc);
    }
    g_attout[head * 128 + t] = acc / denom;
}

// ====================================================================
extern "C" void kernel_launch(void* const* d_in, const int* in_sizes, int n_in,
                              void* d_out, int out_size)
{
    const float* x    = (const float*)d_in[0];
    const float* wqkv = (const float*)d_in[1];
    const float* wo   = (const float*)d_in[2];
    const float* rot  = (const float*)d_in[3];
    const float* ck   = (const float*)d_in[4];
    const float* cv   = (const float*)d_in[5];
    float* out = (float*)d_out;

    static int smem_set = 0;
    if (!smem_set) {
        cudaFuncSetAttribute(attn_group,
                             cudaFuncAttributeMaxDynamicSharedMemorySize,
                             ATT_SMEM_);
        smem_set = 1;
    }

    // 1) QKV projection (split-K 16) + reduce
    gemm_part<<<dim3(24, SPLITS_), 128>>>(x, wqkv, QKVD_, 0);
    reduce_part<<<768, 256>>>(nullptr, B_ * QKVD_, 1);

    // 2) RoPE
    rope_kernel<<<1280, 128>>>(rot);

    // 3) pipelined flash-decode attention (16 groups x 4 chunks x 32 keys)
    attn_group<<<dim3(NBKV_, NCHG_), 256, ATT_SMEM_>>>(ck, cv);
    combine_kernel<<<NHEAD_, 128>>>();

    // 4) output projection + reduce into d_out
    gemm_part<<<dim3(16, SPLITS_), 128>>>(nullptr, wo, HID_, 1);
    reduce_part<<<512, 256>>>(out, B_ * HID_, 0);
}

// round 8
// speedup vs baseline: 1.8765x; 1.5018x over previous
#include <cuda_runtime.h>
#include <cuda_bf16.h>

// ---------------- problem constants (dataset-fixed) ----------------
#define B_    32
#define H_    32
#define KVH_  8
#define G_    4
#define D_    128
#define SW_   4096
#define HID_  4096
#define QKVD_ 6144
#define POS_  2047          // current_pos (dataset constant)
#define L_    2048          // min(current_pos+1, SW)
#define CH_   32            // keys per attention chunk
#define CPG_  4             // chunks per block (pipelined)
#define NCHG_ 16            // chunk groups = L/(CH*CPG)
#define NHEAD_ 1024         // B * H
#define NBKV_  256          // B * KVH
#define SPLITS_ 16
#define KC_     (HID_ / SPLITS_)   // 256
#define KSTR_   66          // attn K row stride in u64 (16B-aligned, cp16-able)

typedef unsigned long long u64;

// ---------------- scratch (no allocations allowed) ----------------
__device__ __align__(16) float g_part[SPLITS_ * B_ * QKVD_];
__device__ __align__(16) float g_xqkv[B_ * QKVD_];
__device__ __align__(16) float g_q[B_ * H_ * D_];
__device__ __align__(16) float g_knew[B_ * KVH_ * D_];
__device__ __align__(16) float g_vnew[B_ * KVH_ * D_];
__device__ __align__(16) float g_attout[B_ * HID_];
__device__ __align__(16) float g_pml[NCHG_ * NHEAD_ * 2];
__device__ __align__(16) float g_po [NCHG_ * NHEAD_ * D_];

// ---------------- f32x2 / async helpers ----------------
__device__ __forceinline__ u64 pack2(float lo, float hi) {
    u64 r; asm("mov.b64 %0, {%1, %2};" : "=l"(r) : "f"(lo), "f"(hi)); return r;
}
__device__ __forceinline__ void unpack2(u64 v, float& lo, float& hi) {
    asm("mov.b64 {%0, %1}, %2;" : "=f"(lo), "=f"(hi) : "l"(v));
}
__device__ __forceinline__ u64 fma2(u64 a, u64 b, u64 c) {
    u64 d; asm("fma.rn.f32x2 %0, %1, %2, %3;" : "=l"(d) : "l"(a), "l"(b), "l"(c)); return d;
}
__device__ __forceinline__ unsigned su32(const void* p) {
    return (unsigned)__cvta_generic_to_shared(p);
}
__device__ __forceinline__ void cp16(unsigned dst, const void* src) {
    asm volatile("cp.async.cg.shared.global [%0], [%1], 16;" :: "r"(dst), "l"(src));
}
__device__ __forceinline__ void cp_commit() {
    asm volatile("cp.async.commit_group;");
}

// ====================================================================
// Split-K GEMM, cp.async pipelined.
// Block = 128 threads, 256 cols (2 adjacent per thread), split-K 16.
// X chunk [32 m][256 k] staged ONCE, transposed to xs[k][m] (rows
// 36-float stride; inner reads are broadcast LDS.64).
// W streamed as 32 tiles of [8 k][256 j] through a 3-deep cp.async ring:
// DRAM latency never exposed; FFMA2 is the binding pipe.
// smem = 256*36*4 + 3*8*256*4 = 61440 B -> 3 blocks/SM.
// ====================================================================
#define GEMM_SMEM_ 61440

__global__ __launch_bounds__(128) void gemm_part(const float* __restrict__ Xin,
                                                 const float* __restrict__ W,
                                                 int N, int use_attout)
{
    extern __shared__ float gsm[];
    float* xs = gsm;                    // [256 k][36] (m in first 32)
    float* WT = gsm + KC_ * 36;         // [3][8][256]

    const float* __restrict__ X = use_attout ? g_attout : Xin;
    const int t  = threadIdx.x;            // 0..127
    const int j0 = blockIdx.x * 256;
    const int j  = j0 + 2 * t;
    const int k0 = blockIdx.y * KC_;

    // ---- W tile loader (8 rows x 256 cols = 512 float4, 4/thread) ----
    auto issue_tile = [&](int ti) {
        float* dst = WT + (ti % 3) * 8 * 256;
        const float* src = W + (size_t)(k0 + ti * 8) * N + j0;
#pragma unroll
        for (int i = 0; i < 4; i++) {
            int slot = t + 128 * i;          // 0..511
            int r  = slot >> 6;              // 0..7
            int c4 = slot & 63;
            cp16(su32(dst + r * 256 + c4 * 4), src + (size_t)r * N + c4 * 4);
        }
        cp_commit();
    };

    issue_tile(0);
    issue_tile(1);

    // ---- stage X chunk transposed: 2048 float4 slots, 16/thread ----
#pragma unroll
    for (int i = 0; i < 16; i++) {
        int slot = t + 128 * i;              // 0..2047
        int m  = slot >> 6;                  // 0..31
        int c4 = slot & 63;                  // 0..63
        const float4 v = *(const float4*)&X[m * HID_ + k0 + c4 * 4];
        xs[(c4 * 4 + 0) * 36 + m] = v.x;
        xs[(c4 * 4 + 1) * 36 + m] = v.y;
        xs[(c4 * 4 + 2) * 36 + m] = v.z;
        xs[(c4 * 4 + 3) * 36 + m] = v.w;
    }

    u64 acc[16][2];
#pragma unroll
    for (int r = 0; r < 16; r++) { acc[r][0] = 0ULL; acc[r][1] = 0ULL; }

#pragma unroll 1
    for (int ti = 0; ti < 32; ti++) {
        if (ti < 31) asm volatile("cp.async.wait_group 1;");
        else         asm volatile("cp.async.wait_group 0;");
        __syncthreads();                      // tile ti visible; tile ti-1 compute done
        if (ti + 2 < 32) issue_tile(ti + 2);  // overwrites tile (ti-1)'s buffer

        const float* wt = WT + (ti % 3) * 8 * 256;
#pragma unroll
        for (int kk = 0; kk < 8; kk++) {
            const u64 w2 = *(const u64*)&wt[kk * 256 + 2 * t];  // cols j, j+1
            float wx, wy;
            unpack2(w2, wx, wy);
            const u64 w0 = pack2(wx, wx);
            const u64 w1 = pack2(wy, wy);
            const u64* xr = (const u64*)&xs[(ti * 8 + kk) * 36]; // 16 row-pairs, broadcast
#pragma unroll
            for (int r = 0; r < 16; r++) {
                u64 x2 = xr[r];
                acc[r][0] = fma2(x2, w0, acc[r][0]);
                acc[r][1] = fma2(x2, w1, acc[r][1]);
            }
        }
    }

    float* op = g_part + (size_t)blockIdx.y * 32 * N;
#pragma unroll
    for (int r = 0; r < 16; r++) {
        float a, b;
        unpack2(acc[r][0], a, b);
        op[(size_t)(2 * r) * N + j]         = a;
        op[(size_t)(2 * r + 1) * N + j]     = b;
        unpack2(acc[r][1], a, b);
        op[(size_t)(2 * r) * N + j + 1]     = a;
        op[(size_t)(2 * r + 1) * N + j + 1] = b;
    }
}

// ---------------- split-K reduction ----------------
__global__ void reduce_part(float* __restrict__ outp, int total, int to_xqkv)
{
    float* o = to_xqkv ? g_xqkv : outp;
    int i = blockIdx.x * 256 + threadIdx.x;
    float a = 0.f;
#pragma unroll
    for (int s = 0; s < SPLITS_; s++) a += g_part[(size_t)s * total + i];
    o[i] = a;
}

// ====================================================================
// RoPE
// ====================================================================
__global__ void rope_kernel(const float* __restrict__ rot)
{
    __shared__ float xr[128];
    const int t   = threadIdx.x;
    const int blk = blockIdx.x;

    if (blk < 1024) {
        int b = blk >> 5, h = blk & 31;
        xr[t] = g_xqkv[b * QKVD_ + h * 128 + t];
        __syncthreads();
        float acc = 0.f;
#pragma unroll 8
        for (int d = 0; d < 128; d++)
            acc = fmaf(xr[d], rot[d * 128 + t], acc);
        g_q[blk * 128 + t] = acc * 0.08838834764831845f;
    } else {
        int kv = blk - 1024;
        int b = kv >> 3, kvh = kv & 7;
        xr[t] = g_xqkv[b * QKVD_ + 4096 + kvh * 128 + t];
        g_vnew[kv * 128 + t] = g_xqkv[b * QKVD_ + 5120 + kvh * 128 + t];
        __syncthreads();
        float acc = 0.f;
#pragma unroll 8
        for (int d = 0; d < 128; d++)
            acc = fmaf(xr[d], rot[d * 128 + t], acc);
        g_knew[kv * 128 + t] = acc;
    }
}

// ====================================================================
// Pipelined flash-decode attention (as R7) with K rows stride 66 u64:
// 16B-aligned -> single cp16 per slot (was 2x cp8), cutting LSU work
// by a third. Cost: benign 2-way bank conflict on score-phase LDS.64.
// ====================================================================
#define ATT_SMEM_ (33792 + 32768 + 2048 + 4096 + 512 + 64)

__global__ __launch_bounds__(256) void attn_group(const float* __restrict__ cache_k,
                                                  const float* __restrict__ cache_v)
{
    extern __shared__ char smem_raw[];
    u64*    kbuf  = (u64*)smem_raw;                  // [2][32*66]
    u64*    vbuf  = kbuf + 2 * 32 * KSTR_;           // [2][32*64]
    float4* qs    = (float4*)(vbuf + 2 * 32 * 64);   // [4*32]
    float*  ss    = (float*)(qs + 128);              // [8dc][4g][32p]
    float*  probs = ss + 1024;                       // [4g][32p]
    float*  Msm   = probs + 128;                     // [4]
    float*  Lsm   = Msm + 4;                         // [4]
    float*  Asm   = Lsm + 4;                         // [4] alpha

    const int t   = threadIdx.x;       // 0..255
    const int bkv = blockIdx.x;        // b*8 + kvh
    const int grp = blockIdx.y;        // chunk group
    const int c0  = grp * CPG_;

    if (t < 128) {
        int g = t >> 5, dq = t & 31;
        qs[g * 32 + dq] = *(const float4*)&g_q[(bkv * 4 + g) * 128 + dq * 4];
    }
    if (t < 4) { Msm[t] = -1e30f; Lsm[t] = 0.f; }

    auto issue_chunk = [&](int cc, int buf) {
        const int p0 = (c0 + cc) * CH_;
        u64* kb = kbuf + buf * 32 * KSTR_;
        u64* vb = vbuf + buf * 32 * 64;
#pragma unroll
        for (int i = 0; i < 4; i++) {
            int slot = t + 256 * i;            // 0..1023
            int p = slot >> 5, dq = slot & 31;
            int gp = p0 + p;
            const float* ks = (gp == POS_)
                ? (g_knew + bkv * D_)
                : (cache_k + ((size_t)bkv * SW_ + gp) * D_);
            cp16(su32(kb + p * KSTR_ + dq * 2), ks + dq * 4);
        }
#pragma unroll
        for (int i = 0; i < 4; i++) {
            int slot = t + 256 * i;
            int p = slot >> 5, dq = slot & 31;
            int gp = p0 + p;
            const float* vs = (gp == POS_)
                ? (g_vnew + bkv * D_)
                : (cache_v + ((size_t)bkv * SW_ + gp) * D_);
            cp16(su32(vb + p * 64 + dq * 2), vs + dq * 4);
        }
        cp_commit();
    };

    issue_chunk(0, 0);

    u64 O = 0ULL;                      // running output: thread (g = t>>6, d2 = t&63)
    const int pvg  = t >> 6;
    const int pvd2 = t & 63;

#pragma unroll 1
    for (int cc = 0; cc < CPG_; cc++) {
        const int buf = cc & 1;
        if (cc < CPG_ - 1) {
            issue_chunk(cc + 1, buf ^ 1);
            asm volatile("cp.async.wait_group 1;");
        } else {
            asm volatile("cp.async.wait_group 0;");
        }
        __syncthreads();

        const u64* kb = kbuf + buf * 32 * KSTR_;
        const u64* vb = vbuf + buf * 32 * 64;

        // scores: thread = (p = t&31, dc = t>>5 of 8); 16 d (8 u64) each
        {
            int p = t & 31, dc = t >> 5;
            const u64* kp = kb + p * KSTR_ + dc * 8;
            const u64* q2 = (const u64*)qs;
            u64 a0 = 0ULL, a1 = 0ULL, a2 = 0ULL, a3 = 0ULL;
#pragma unroll
            for (int i = 0; i < 8; i++) {
                u64 k2 = kp[i];
                int qi = dc * 8 + i;
                a0 = fma2(k2, q2[qi],       a0);
                a1 = fma2(k2, q2[64 + qi],  a1);
                a2 = fma2(k2, q2[128 + qi], a2);
                a3 = fma2(k2, q2[192 + qi], a3);
            }
            float lo, hi;
            unpack2(a0, lo, hi); ss[(dc * 4 + 0) * 32 + p] = lo + hi;
            unpack2(a1, lo, hi); ss[(dc * 4 + 1) * 32 + p] = lo + hi;
            unpack2(a2, lo, hi); ss[(dc * 4 + 2) * 32 + p] = lo + hi;
            unpack2(a3, lo, hi); ss[(dc * 4 + 3) * 32 + p] = lo + hi;
        }
        __syncthreads();

        // sum d-chunks + online softmax update: warp g (t<128)
        if (t < 128) {
            int g = t >> 5, p = t & 31;
            float s = 0.f;
#pragma unroll
            for (int dc = 0; dc < 8; dc++)
                s += ss[(dc * 4 + g) * 32 + p];

            float mc = s;
#pragma unroll
            for (int o = 16; o > 0; o >>= 1)
                mc = fmaxf(mc, __shfl_xor_sync(0xffffffffu, mc, o));
            float Mold = Msm[g];
            float Mnew = fmaxf(Mold, mc);
            float e = __expf(s - Mnew);
            probs[g * 32 + p] = e;
            float l = e;
#pragma unroll
            for (int o = 16; o > 0; o >>= 1)
                l += __shfl_xor_sync(0xffffffffu, l, o);
            if (p == 0) {
                float alpha = __expf(Mold - Mnew);
                Asm[g] = alpha;
                Lsm[g] = Lsm[g] * alpha + l;
                Msm[g] = Mnew;
            }
        }
        __syncthreads();

        // pv with online rescale: thread = (g = t>>6, d2 = t&63)
        {
            float alpha = Asm[pvg];
            O = fma2(O, pack2(alpha, alpha), 0ULL);
            const float* pr = probs + pvg * 32;
#pragma unroll
            for (int p = 0; p < 32; p++) {
                float w = pr[p];
                O = fma2(vb[p * 64 + pvd2], pack2(w, w), O);
            }
        }
        __syncthreads();
    }

    // epilogue: one partial per group
    {
        int head = bkv * 4 + pvg;
        float o0, o1;
        unpack2(O, o0, o1);
        float2* dst = (float2*)&g_po[((size_t)grp * NHEAD_ + head) * D_ + pvd2 * 2];
        *dst = make_float2(o0, o1);
    }
    if (t < 4) {
        int head = bkv * 4 + t;
        g_pml[(grp * NHEAD_ + head) * 2 + 0] = Msm[t];
        g_pml[(grp * NHEAD_ + head) * 2 + 1] = Lsm[t];
    }
}

// ---------------- combine per-group softmax partials ----------------
__global__ void combine_kernel()
{
    const int head = blockIdx.x;
    const int t    = threadIdx.x;

    float M = -1e30f;
#pragma unroll
    for (int c = 0; c < NCHG_; c++)
        M = fmaxf(M, g_pml[(c * NHEAD_ + head) * 2]);

    float denom = 0.f, acc = 0.f;
#pragma unroll
    for (int c = 0; c < NCHG_; c++) {
        float m = g_pml[(c * NHEAD_ + head) * 2 + 0];
        float l = g_pml[(c * NHEAD_ + head) * 2 + 1];
        float w = __expf(m - M);
        denom += w * l;
        acc = fmaf(w, g_po[((size_t)c * NHEAD_ + head) * D_ + t], acc);
    }
    g_attout[head * 128 + t] = acc / denom;
}

// ====================================================================
extern "C" void kernel_launch(void* const* d_in, const int* in_sizes, int n_in,
                              void* d_out, int out_size)
{
    const float* x    = (const float*)d_in[0];
    const float* wqkv = (const float*)d_in[1];
    const float* wo   = (const float*)d_in[2];
    const float* rot  = (const float*)d_in[3];
    const float* ck   = (const float*)d_in[4];
    const float* cv   = (const float*)d_in[5];
    float* out = (float*)d_out;

    static int smem_set = 0;
    if (!smem_set) {
        cudaFuncSetAttribute(attn_group,
                             cudaFuncAttributeMaxDynamicSharedMemorySize,
                             ATT_SMEM_);
        cudaFuncSetAttribute(gemm_part,
                             cudaFuncAttributeMaxDynamicSharedMemorySize,
                             GEMM_SMEM_);
        smem_set = 1;
    }

    // 1) QKV projection (split-K 16, pipelined) + reduce
    gemm_part<<<dim3(24, SPLITS_), 128, GEMM_SMEM_>>>(x, wqkv, QKVD_, 0);
    reduce_part<<<768, 256>>>(nullptr, B_ * QKVD_, 1);

    // 2) RoPE
    rope_kernel<<<1280, 128>>>(rot);

    // 3) pipelined flash-decode attention (16 groups x 4 chunks x 32 keys)
    attn_group<<<dim3(NBKV_, NCHG_), 256, ATT_SMEM_>>>(ck, cv);
    combine_kernel<<<NHEAD_, 128>>>();

    // 4) output projection (pipelined) + reduce into d_out
    gemm_part<<<dim3(16, SPLITS_), 128, GEMM_SMEM_>>>(nullptr, wo, HID_, 1);
    reduce_part<<<512, 256>>>(out, B_ * HID_, 0);
}

// round 9
// speedup vs baseline: 1.8841x; 1.0040x over previous
#include <cuda_runtime.h>
#include <cuda_bf16.h>

// ---------------- problem constants (dataset-fixed) ----------------
#define B_    32
#define H_    32
#define KVH_  8
#define G_    4
#define D_    128
#define SW_   4096
#define HID_  4096
#define QKVD_ 6144
#define POS_  2047          // current_pos (dataset constant)
#define L_    2048          // min(current_pos+1, SW)
#define CH_   32            // keys per attention chunk
#define CPG_  8             // chunks per block (pipelined)
#define NCHG_ 8             // chunk groups = L/(CH*CPG)
#define NHEAD_ 1024         // B * H
#define NBKV_  256          // B * KVH
#define SPLITS_ 16
#define KC_     (HID_ / SPLITS_)   // 256
#define KSTR_   66          // attn K row stride in u64 (16B-aligned, cp16-able)
#define BQ_     (B_ * QKVD_)       // g_part slice stride for QKV

typedef unsigned long long u64;

// ---------------- scratch (no allocations allowed) ----------------
__device__ __align__(16) float g_part[SPLITS_ * B_ * QKVD_];
__device__ __align__(16) float g_q[B_ * H_ * D_];
__device__ __align__(16) float g_knew[B_ * KVH_ * D_];
__device__ __align__(16) float g_vnew[B_ * KVH_ * D_];
__device__ __align__(16) float g_attout[B_ * HID_];
__device__ __align__(16) float g_pml[NCHG_ * NHEAD_ * 2];
__device__ __align__(16) float g_po [NCHG_ * NHEAD_ * D_];

// ---------------- f32x2 / async helpers ----------------
__device__ __forceinline__ u64 pack2(float lo, float hi) {
    u64 r; asm("mov.b64 %0, {%1, %2};" : "=l"(r) : "f"(lo), "f"(hi)); return r;
}
__device__ __forceinline__ void unpack2(u64 v, float& lo, float& hi) {
    asm("mov.b64 {%0, %1}, %2;" : "=f"(lo), "=f"(hi) : "l"(v));
}
__device__ __forceinline__ u64 fma2(u64 a, u64 b, u64 c) {
    u64 d; asm("fma.rn.f32x2 %0, %1, %2, %3;" : "=l"(d) : "l"(a), "l"(b), "l"(c)); return d;
}
__device__ __forceinline__ unsigned su32(const void* p) {
    return (unsigned)__cvta_generic_to_shared(p);
}
__device__ __forceinline__ void cp16(unsigned dst, const void* src) {
    asm volatile("cp.async.cg.shared.global [%0], [%1], 16;" :: "r"(dst), "l"(src));
}
__device__ __forceinline__ void cp_commit() {
    asm volatile("cp.async.commit_group;");
}

// ====================================================================
// Split-K GEMM, cp.async pipelined (4-deep W ring, 2 groups in flight).
// Block = 128 threads, 256 cols (2 per thread), split-K 16.
// X chunk [32 m][256 k] staged once transposed (broadcast LDS.64 reads).
// W streamed as 32 tiles of [8 k][256 j].
// smem = 256*36*4 + 4*8*256*4 = 69632 B -> 3 blocks/SM.
// ====================================================================
#define GEMM_SMEM_ 69632

__global__ __launch_bounds__(128) void gemm_part(const float* __restrict__ Xin,
                                                 const float* __restrict__ W,
                                                 int N, int use_attout)
{
    extern __shared__ float gsm[];
    float* xs = gsm;                    // [256 k][36] (m in first 32)
    float* WT = gsm + KC_ * 36;         // [4][8][256]

    const float* __restrict__ X = use_attout ? g_attout : Xin;
    const int t  = threadIdx.x;            // 0..127
    const int j0 = blockIdx.x * 256;
    const int j  = j0 + 2 * t;
    const int k0 = blockIdx.y * KC_;

    auto issue_tile = [&](int ti) {
        float* dst = WT + (ti & 3) * 8 * 256;
        const float* src = W + (size_t)(k0 + ti * 8) * N + j0;
#pragma unroll
        for (int i = 0; i < 4; i++) {
            int slot = t + 128 * i;          // 0..511
            int r  = slot >> 6;              // 0..7
            int c4 = slot & 63;
            cp16(su32(dst + r * 256 + c4 * 4), src + (size_t)r * N + c4 * 4);
        }
        cp_commit();
    };

    issue_tile(0);
    issue_tile(1);
    issue_tile(2);

    // stage X chunk transposed: 2048 float4 slots, 16/thread
#pragma unroll
    for (int i = 0; i < 16; i++) {
        int slot = t + 128 * i;              // 0..2047
        int m  = slot >> 6;                  // 0..31
        int c4 = slot & 63;                  // 0..63
        const float4 v = *(const float4*)&X[m * HID_ + k0 + c4 * 4];
        xs[(c4 * 4 + 0) * 36 + m] = v.x;
        xs[(c4 * 4 + 1) * 36 + m] = v.y;
        xs[(c4 * 4 + 2) * 36 + m] = v.z;
        xs[(c4 * 4 + 3) * 36 + m] = v.w;
    }

    u64 acc[16][2];
#pragma unroll
    for (int r = 0; r < 16; r++) { acc[r][0] = 0ULL; acc[r][1] = 0ULL; }

#pragma unroll 1
    for (int ti = 0; ti < 32; ti++) {
        // allow min(2, 31-ti) groups outstanding -> tile ti complete
        if (ti <= 29)      asm volatile("cp.async.wait_group 2;");
        else if (ti == 30) asm volatile("cp.async.wait_group 1;");
        else               asm volatile("cp.async.wait_group 0;");
        __syncthreads();                      // all threads done with tile ti-1
        if (ti + 3 < 32) issue_tile(ti + 3);  // reuses tile (ti-1)'s buffer

        const float* wt = WT + (ti & 3) * 8 * 256;
#pragma unroll
        for (int kk = 0; kk < 8; kk++) {
            const u64 w2 = *(const u64*)&wt[kk * 256 + 2 * t];  // cols j, j+1
            float wx, wy;
            unpack2(w2, wx, wy);
            const u64 w0 = pack2(wx, wx);
            const u64 w1 = pack2(wy, wy);
            const u64* xr = (const u64*)&xs[(ti * 8 + kk) * 36];
#pragma unroll
            for (int r = 0; r < 16; r++) {
                u64 x2 = xr[r];
                acc[r][0] = fma2(x2, w0, acc[r][0]);
                acc[r][1] = fma2(x2, w1, acc[r][1]);
            }
        }
    }

    float* op = g_part + (size_t)blockIdx.y * 32 * N;
#pragma unroll
    for (int r = 0; r < 16; r++) {
        float a, b;
        unpack2(acc[r][0], a, b);
        op[(size_t)(2 * r) * N + j]         = a;
        op[(size_t)(2 * r + 1) * N + j]     = b;
        unpack2(acc[r][1], a, b);
        op[(size_t)(2 * r) * N + j + 1]     = a;
        op[(size_t)(2 * r + 1) * N + j + 1] = b;
    }
}

// ---------------- split-K reduction (WO output only) ----------------
__global__ void reduce_part(float* __restrict__ outp, int total)
{
    int i = blockIdx.x * 256 + threadIdx.x;
    float a = 0.f;
#pragma unroll
    for (int s = 0; s < SPLITS_; s++) a += g_part[(size_t)s * total + i];
    outp[i] = a;
}

// ====================================================================
// RoPE with fused QKV split-K reduction: reads the 16 g_part slices
// directly (coalesced, stride BQ_), reduces, then rotates.
// Blocks 0..1023: q head (b,h). Blocks 1024..1279: k/v head (b,kvh).
// ====================================================================
__device__ __forceinline__ float part_sum(int idx)
{
    float a = 0.f;
#pragma unroll
    for (int s = 0; s < SPLITS_; s++) a += g_part[(size_t)s * BQ_ + idx];
    return a;
}

__global__ void rope_kernel(const float* __restrict__ rot)
{
    __shared__ float xr[128];
    const int t   = threadIdx.x;
    const int blk = blockIdx.x;

    if (blk < 1024) {
        int b = blk >> 5, h = blk & 31;
        xr[t] = part_sum(b * QKVD_ + h * 128 + t);
        __syncthreads();
        float acc = 0.f;
#pragma unroll 8
        for (int d = 0; d < 128; d++)
            acc = fmaf(xr[d], rot[d * 128 + t], acc);
        g_q[blk * 128 + t] = acc * 0.08838834764831845f;   // D^-0.5
    } else {
        int kv = blk - 1024;
        int b = kv >> 3, kvh = kv & 7;
        xr[t] = part_sum(b * QKVD_ + 4096 + kvh * 128 + t);
        g_vnew[kv * 128 + t] = part_sum(b * QKVD_ + 5120 + kvh * 128 + t);
        __syncthreads();
        float acc = 0.f;
#pragma unroll 8
        for (int d = 0; d < 128; d++)
            acc = fmaf(xr[d], rot[d * 128 + t], acc);
        g_knew[kv * 128 + t] = acc;
    }
}

// ====================================================================
// Pipelined flash-decode attention: one (bkv, group of 8 chunks of 32
// keys) per 256-thread block; double-buffered cp.async K/V tiles,
// online softmax merge in registers, one partial per group.
// ====================================================================
#define ATT_SMEM_ (33792 + 32768 + 2048 + 4096 + 512 + 64)

__global__ __launch_bounds__(256) void attn_group(const float* __restrict__ cache_k,
                                                  const float* __restrict__ cache_v)
{
    extern __shared__ char smem_raw[];
    u64*    kbuf  = (u64*)smem_raw;                  // [2][32*66]
    u64*    vbuf  = kbuf + 2 * 32 * KSTR_;           // [2][32*64]
    float4* qs    = (float4*)(vbuf + 2 * 32 * 64);   // [4*32]
    float*  ss    = (float*)(qs + 128);              // [8dc][4g][32p]
    float*  probs = ss + 1024;                       // [4g][32p]
    float*  Msm   = probs + 128;                     // [4]
    float*  Lsm   = Msm + 4;                         // [4]
    float*  Asm   = Lsm + 4;                         // [4] alpha

    const int t   = threadIdx.x;       // 0..255
    const int bkv = blockIdx.x;        // b*8 + kvh
    const int grp = blockIdx.y;        // chunk group
    const int c0  = grp * CPG_;

    if (t < 128) {
        int g = t >> 5, dq = t & 31;
        qs[g * 32 + dq] = *(const float4*)&g_q[(bkv * 4 + g) * 128 + dq * 4];
    }
    if (t < 4) { Msm[t] = -1e30f; Lsm[t] = 0.f; }

    auto issue_chunk = [&](int cc, int buf) {
        const int p0 = (c0 + cc) * CH_;
        u64* kb = kbuf + buf * 32 * KSTR_;
        u64* vb = vbuf + buf * 32 * 64;
#pragma unroll
        for (int i = 0; i < 4; i++) {
            int slot = t + 256 * i;            // 0..1023
            int p = slot >> 5, dq = slot & 31;
            int gp = p0 + p;
            const float* ks = (gp == POS_)
                ? (g_knew + bkv * D_)
                : (cache_k + ((size_t)bkv * SW_ + gp) * D_);
            cp16(su32(kb + p * KSTR_ + dq * 2), ks + dq * 4);
        }
#pragma unroll
        for (int i = 0; i < 4; i++) {
            int slot = t + 256 * i;
            int p = slot >> 5, dq = slot & 31;
            int gp = p0 + p;
            const float* vs = (gp == POS_)
                ? (g_vnew + bkv * D_)
                : (cache_v + ((size_t)bkv * SW_ + gp) * D_);
            cp16(su32(vb + p * 64 + dq * 2), vs + dq * 4);
        }
        cp_commit();
    };

    issue_chunk(0, 0);

    u64 O = 0ULL;                      // running output: thread (g = t>>6, d2 = t&63)
    const int pvg  = t >> 6;
    const int pvd2 = t & 63;

#pragma unroll 1
    for (int cc = 0; cc < CPG_; cc++) {
        const int buf = cc & 1;
        if (cc < CPG_ - 1) {
            issue_chunk(cc + 1, buf ^ 1);
            asm volatile("cp.async.wait_group 1;");
        } else {
            asm volatile("cp.async.wait_group 0;");
        }
        __syncthreads();

        const u64* kb = kbuf + buf * 32 * KSTR_;
        const u64* vb = vbuf + buf * 32 * 64;

        // scores: thread = (p = t&31, dc = t>>5 of 8); 16 d (8 u64) each
        {
            int p = t & 31, dc = t >> 5;
            const u64* kp = kb + p * KSTR_ + dc * 8;
            const u64* q2 = (const u64*)qs;
            u64 a0 = 0ULL, a1 = 0ULL, a2 = 0ULL, a3 = 0ULL;
#pragma unroll
            for (int i = 0; i < 8; i++) {
                u64 k2 = kp[i];
                int qi = dc * 8 + i;
                a0 = fma2(k2, q2[qi],       a0);
                a1 = fma2(k2, q2[64 + qi],  a1);
                a2 = fma2(k2, q2[128 + qi], a2);
                a3 = fma2(k2, q2[192 + qi], a3);
            }
            float lo, hi;
            unpack2(a0, lo, hi); ss[(dc * 4 + 0) * 32 + p] = lo + hi;
            unpack2(a1, lo, hi); ss[(dc * 4 + 1) * 32 + p] = lo + hi;
            unpack2(a2, lo, hi); ss[(dc * 4 + 2) * 32 + p] = lo + hi;
            unpack2(a3, lo, hi); ss[(dc * 4 + 3) * 32 + p] = lo + hi;
        }
        __syncthreads();

        // sum d-chunks + online softmax update: warp g (t<128)
        if (t < 128) {
            int g = t >> 5, p = t & 31;
            float s = 0.f;
#pragma unroll
            for (int dc = 0; dc < 8; dc++)
                s += ss[(dc * 4 + g) * 32 + p];

            float mc = s;
#pragma unroll
            for (int o = 16; o > 0; o >>= 1)
                mc = fmaxf(mc, __shfl_xor_sync(0xffffffffu, mc, o));
            float Mold = Msm[g];
            float Mnew = fmaxf(Mold, mc);
            float e = __expf(s - Mnew);
            probs[g * 32 + p] = e;
            float l = e;
#pragma unroll
            for (int o = 16; o > 0; o >>= 1)
                l += __shfl_xor_sync(0xffffffffu, l, o);
            if (p == 0) {
                float alpha = __expf(Mold - Mnew);
                Asm[g] = alpha;
                Lsm[g] = Lsm[g] * alpha + l;
                Msm[g] = Mnew;
            }
        }
        __syncthreads();

        // pv with online rescale: thread = (g = t>>6, d2 = t&63)
        {
            float alpha = Asm[pvg];
            O = fma2(O, pack2(alpha, alpha), 0ULL);
            const float* pr = probs + pvg * 32;
#pragma unroll
            for (int p = 0; p < 32; p++) {
                float w = pr[p];
                O = fma2(vb[p * 64 + pvd2], pack2(w, w), O);
            }
        }
        __syncthreads();
    }

    // epilogue: one partial per group
    {
        int head = bkv * 4 + pvg;
        float o0, o1;
        unpack2(O, o0, o1);
        float2* dst = (float2*)&g_po[((size_t)grp * NHEAD_ + head) * D_ + pvd2 * 2];
        *dst = make_float2(o0, o1);
    }
    if (t < 4) {
        int head = bkv * 4 + t;
        g_pml[(grp * NHEAD_ + head) * 2 + 0] = Msm[t];
        g_pml[(grp * NHEAD_ + head) * 2 + 1] = Lsm[t];
    }
}

// ---------------- combine per-group softmax partials ----------------
__global__ void combine_kernel()
{
    const int head = blockIdx.x;
    const int t    = threadIdx.x;

    float M = -1e30f;
#pragma unroll
    for (int c = 0; c < NCHG_; c++)
        M = fmaxf(M, g_pml[(c * NHEAD_ + head) * 2]);

    float denom = 0.f, acc = 0.f;
#pragma unroll
    for (int c = 0; c < NCHG_; c++) {
        float m = g_pml[(c * NHEAD_ + head) * 2 + 0];
        float l = g_pml[(c * NHEAD_ + head) * 2 + 1];
        float w = __expf(m - M);
        denom += w * l;
        acc = fmaf(w, g_po[((size_t)c * NHEAD_ + head) * D_ + t], acc);
    }
    g_attout[head * 128 + t] = acc / denom;
}

// ====================================================================
extern "C" void kernel_launch(void* const* d_in, const int* in_sizes, int n_in,
                              void* d_out, int out_size)
{
    const float* x    = (const float*)d_in[0];
    const float* wqkv = (const float*)d_in[1];
    const float* wo   = (const float*)d_in[2];
    const float* rot  = (const float*)d_in[3];
    const float* ck   = (const float*)d_in[4];
    const float* cv   = (const float*)d_in[5];
    float* out = (float*)d_out;

    static int smem_set = 0;
    if (!smem_set) {
        cudaFuncSetAttribute(attn_group,
                             cudaFuncAttributeMaxDynamicSharedMemorySize,
                             ATT_SMEM_);
        cudaFuncSetAttribute(gemm_part,
                             cudaFuncAttributeMaxDynamicSharedMemorySize,
                             GEMM_SMEM_);
        smem_set = 1;
    }

    // 1) QKV projection (split-K 16, pipelined)
    gemm_part<<<dim3(24, SPLITS_), 128, GEMM_SMEM_>>>(x, wqkv, QKVD_, 0);

    // 2) RoPE with fused split-K reduction
    rope_kernel<<<1280, 128>>>(rot);

    // 3) pipelined flash-decode attention (8 groups x 8 chunks x 32 keys)
    attn_group<<<dim3(NBKV_, NCHG_), 256, ATT_SMEM_>>>(ck, cv);
    combine_kernel<<<NHEAD_, 128>>>();

    // 4) output projection (pipelined) + reduce into d_out
    gemm_part<<<dim3(16, SPLITS_), 128, GEMM_SMEM_>>>(nullptr, wo, HID_, 1);
    reduce_part<<<512, 256>>>(out, B_ * HID_);
}